// round 1
// baseline (speedup 1.0000x reference)
#include <cuda_runtime.h>

// CTC batch cost (Keras ctc_batch_cost semantics), blank = V-1.
// B=256, T=512, V=256, L=64, S=2L+1=129.
// One block per batch element; thread s owns extended-label state s.
// Double-buffered alpha in shared memory, one __syncthreads per time step.
// Global gathers of y_pred[b,t,ext[s]] are prefetched PF steps ahead through
// a register ring so DRAM latency overlaps the DP compute chain.

#define B_      256
#define T_      512
#define V_      256
#define L_      64
#define S_      129
#define BLANK_  (V_ - 1)
#define EPS_    1e-7f
#define NEG_    -1e30f
#define NTHREADS 160   // 5 warps; threads [0,129) are DP states
#define PF 8           // prefetch depth (register ring)

__device__ __forceinline__ float lae2(float a, float b) {
    float mx = fmaxf(a, b);
    float mn = fminf(a, b);
    return mx + __logf(1.0f + __expf(mn - mx));
}

__global__ __launch_bounds__(NTHREADS)
void ctc_loss_kernel(const int* __restrict__ y_true,
                     const float* __restrict__ y_pred,
                     float* __restrict__ out)
{
    const int b = blockIdx.x;
    const int s = threadIdx.x;

    // alpha double buffer with 2 leading NEG pad cells so a1/a2 reads need no branch.
    __shared__ float A[2][NTHREADS + 2];
    if (s < 2) { A[0][s] = NEG_; A[1][s] = NEG_; }

    // --- per-thread extended-label setup ---
    int  col  = BLANK_;
    bool skip = false;
    if (s < S_) {
        if (s & 1) {
            col = y_true[b * L_ + (s >> 1)];
            // skip (s-2 -> s) allowed iff label != label two states back
            skip = (s == 1) ? true : (col != y_true[b * L_ + (s >> 1) - 1]);
        }
    }

    const float* p = y_pred + (size_t)b * (T_ * V_) + col;

    // --- prefetch ring: raw probabilities for t = 0..PF-1 ---
    float q[PF];
#pragma unroll
    for (int i = 0; i < PF; i++) q[i] = __ldcs(p + (size_t)i * V_);

    int par = 0;

#pragma unroll 1
    for (int tt = 0; tt < T_; tt += PF) {
#pragma unroll
        for (int i = 0; i < PF; i++) {
            const int t = tt + i;
            const float pv = q[i];
            if (t + PF < T_) q[i] = __ldcs(p + (size_t)(t + PF) * V_);

            const float lp = __logf(pv + EPS_);

            float val;
            if (t == 0) {
                // alpha0: only state 0 (blank) and state 1 (first label) reachable
                val = (s <= 1) ? lp : NEG_;
            } else {
                const float a0 = A[par][s + 2];
                const float a1 = A[par][s + 1];
                const float a2 = skip ? A[par][s] : NEG_;

                // branchless 3-way logaddexp: 2x EX2 + 1x LG2
                const float mx  = fmaxf(a0, a1);
                const float s01 = 1.0f + __expf(fminf(a0, a1) - mx);   // exp(min-max) in [0,1]
                const float d   = a2 - mx;
                const float e   = __expf(-fabsf(d));
                const float sum = (d <= 0.0f) ? (s01 + e) : fmaf(s01, e, 1.0f);
                const float M   = fmaxf(mx, a2);
                val = M + __logf(sum) + lp;
            }

            A[par ^ 1][s + 2] = val;   // other buffer: no WAR hazard before barrier
            __syncthreads();
            par ^= 1;
        }
    }

    // loss = -logaddexp(alpha_T[S-1], alpha_T[S-2])
    if (s == 0) {
        out[b] = -lae2(A[par][S_ + 1], A[par][S_]);
    }
}

extern "C" void kernel_launch(void* const* d_in, const int* in_sizes, int n_in,
                              void* d_out, int out_size) {
    const int*   y_true = (const int*)  d_in[0];
    const float* y_pred = (const float*)d_in[1];
    float*       out    = (float*)      d_out;
    ctc_loss_kernel<<<B_, NTHREADS>>>(y_true, y_pred, out);
}

// round 3
// speedup vs baseline: 1.9931x; 1.9931x over previous
#include <cuda_runtime.h>

// CTC batch cost (Keras ctc_batch_cost), blank = V-1.
// B=256, T=512, V=256, L=64, S=129.
//
// One WARP per batch element. Lane l owns extended states {4l..4l+3}; lane 31
// also owns state 128. DP in PROBABILITY domain with PER-LANE power-of-2
// exponent frames (E[lane]), rescaled every 8 steps. The cross-lane value
// (neighbor's a3) is re-framed by 2^(E_prev - E_me), split into two clamped
// fp32 factors fixed per group. Zero lanes adopt the nearest nonzero lane's
// frame via a lane-tagged max-scan so frontier mass propagates at full
// precision. Inner loop: 1 shuffle + FMA-pipe ops only. No smem, no barriers.

#define B_      256
#define T_      512
#define V_      256
#define L_      64
#define BLANK_  (V_ - 1)
#define EPS_    1e-7f
#define PF      16
#define FULL_   0xffffffffu

__device__ __forceinline__ float exp2i_clamped(int k) {
    k = max(-126, min(127, k));
    return __int_as_float((k + 127) << 23);
}

__global__ __launch_bounds__(32)
void ctc_kernel(const int* __restrict__ y_true,
                const float* __restrict__ y_pred,
                float* __restrict__ out)
{
    const int b    = blockIdx.x;
    const int lane = threadIdx.x;

    // Labels: state 4l+1 -> y[2l], state 4l+3 -> y[2l+1]
    const int lab0  = y_true[b * L_ + 2 * lane];
    const int lab1  = y_true[b * L_ + 2 * lane + 1];
    const int labm1 = __shfl_up_sync(FULL_, lab1, 1);              // y[2l-1]
    const float sk1 = (lane == 0) ? 1.0f : ((lab0 != labm1) ? 1.0f : 0.0f);
    const float sk3 = (lab1 != lab0) ? 1.0f : 0.0f;

    const float* __restrict__ base = y_pred + (size_t)b * (T_ * V_);

    // Prefetch rings (raw probs) for blank / label0 / label1 columns.
    float qb[PF], q1[PF], q3[PF];
#pragma unroll
    for (int i = 0; i < PF; i++) {
        qb[i] = __ldcs(base + i * V_ + BLANK_);
        q1[i] = __ldcs(base + i * V_ + lab0);
        q3[i] = __ldcs(base + i * V_ + lab1);
    }

    float a0, a1, a2 = 0.f, a3 = 0.f, a4 = 0.f;
    int   E  = 0;                                   // per-lane frame: true = val * 2^E
    float s1 = (lane == 0) ? 0.f : 1.f, s2 = 1.f;   // incoming-a3 reframe factors

#define STEP(pvb, pv1, pv3) do {                                   \
        const float _pb = (pvb) + EPS_;                            \
        const float _p1 = (pv1) + EPS_;                            \
        const float _p3 = (pv3) + EPS_;                            \
        const float a3p = __shfl_up_sync(FULL_, a3, 1);            \
        const float a3q = (a3p * s1) * s2;                         \
        const float n0 = (a0 + a3q) * _pb;                         \
        const float n1 = fmaf(sk1, a3q, a0 + a1) * _p1;            \
        const float n2 = (a1 + a2) * _pb;                          \
        const float n3 = fmaf(sk3, a1, a2 + a3) * _p3;             \
        const float n4 = (a3 + a4) * _pb;                          \
        a0 = n0; a1 = n1; a2 = n2; a3 = n3; a4 = n4;               \
    } while (0)

#define RESCALE() do {                                             \
        float m = fmaxf(fmaxf(a0, a1), fmaxf(a2, a3));             \
        m = fmaxf(m, a4);                                          \
        const bool nz = (m > 0.f);                                 \
        if (nz) {                                                  \
            const int e  = ilogbf(m);                              \
            const int h1 = e >> 1, h2 = e - h1;                    \
            const float u1 = exp2i_clamped(-h1);                   \
            const float u2 = exp2i_clamped(-h2);                   \
            a0 = (a0 * u1) * u2; a1 = (a1 * u1) * u2;              \
            a2 = (a2 * u1) * u2; a3 = (a3 * u1) * u2;              \
            a4 = (a4 * u1) * u2;                                   \
            E += e;                                                \
        }                                                          \
        /* zero lanes adopt nearest-left nonzero lane's frame:     \
           lane-tagged inclusive max-scan */                       \
        int key = nz ? ((lane << 15) | (E + 16384)) : -1;          \
        _Pragma("unroll")                                          \
        for (int off = 1; off < 32; off <<= 1) {                   \
            const int kl = __shfl_up_sync(FULL_, key, off);        \
            if (lane >= off) key = max(key, kl);                   \
        }                                                          \
        if (!nz) E = (key & 32767) - 16384;                        \
        const int Ep = __shfl_up_sync(FULL_, E, 1);                \
        const int dE = Ep - E;                                     \
        const int d1 = dE >> 1, d2 = dE - d1;                      \
        s1 = (lane == 0) ? 0.f : exp2i_clamped(d1);                \
        s2 = exp2i_clamped(d2);                                    \
    } while (0)

    // ---- group 0: t=0 init, t=1..15 steps, refill t=16..31 ----
    a0 = (lane == 0) ? (qb[0] + EPS_) : 0.f;
    a1 = (lane == 0) ? (q1[0] + EPS_) : 0.f;
    qb[0] = __ldcs(base + PF * V_ + BLANK_);
    q1[0] = __ldcs(base + PF * V_ + lab0);
    q3[0] = __ldcs(base + PF * V_ + lab1);
#pragma unroll
    for (int i = 1; i < PF; i++) {
        STEP(qb[i], q1[i], q3[i]);
        qb[i] = __ldcs(base + (i + PF) * V_ + BLANK_);
        q1[i] = __ldcs(base + (i + PF) * V_ + lab0);
        q3[i] = __ldcs(base + (i + PF) * V_ + lab1);
        if (i == 7 || i == 15) RESCALE();
    }

    // ---- middle groups ----
#pragma unroll 1
    for (int tt = PF; tt < T_ - PF; tt += PF) {
#pragma unroll
        for (int i = 0; i < PF; i++) {
            STEP(qb[i], q1[i], q3[i]);
            const int tn = tt + i + PF;
            qb[i] = __ldcs(base + tn * V_ + BLANK_);
            q1[i] = __ldcs(base + tn * V_ + lab0);
            q3[i] = __ldcs(base + tn * V_ + lab1);
            if (i == 7 || i == 15) RESCALE();
        }
    }

    // ---- last group: t = T-16 .. T-1, no refill, no rescale needed ----
#pragma unroll
    for (int i = 0; i < PF; i++) {
        STEP(qb[i], q1[i], q3[i]);
    }

    // loss = -( log(alpha[127] + alpha[128]) + E*ln2 ), states on lane 31
    if (lane == 31) {
        const float tot = a3 + a4;
        out[b] = -(logf(tot) + (float)E * 0.6931471805599453f);
    }

#undef STEP
#undef RESCALE
}

extern "C" void kernel_launch(void* const* d_in, const int* in_sizes, int n_in,
                              void* d_out, int out_size) {
    const int*   y_true = (const int*)  d_in[0];
    const float* y_pred = (const float*)d_in[1];
    float*       out    = (float*)      d_out;
    ctc_kernel<<<B_, 32>>>(y_true, y_pred, out);
}

// round 4
// speedup vs baseline: 1.9946x; 1.0008x over previous
#include <cuda_runtime.h>

// CTC batch cost (Keras ctc_batch_cost), blank = V-1.
// B=256, T=512, V=256, L=64, S=129.
//
// One WARP per batch element. Lane l owns extended states {4l..4l+3}; lane 31
// also owns state 128. DP in PROBABILITY domain with PER-LANE power-of-2
// exponent frames (E[lane]), rescaled every 8 steps. The cross-lane value
// (neighbor's a3) is re-framed by 2^(E_prev - E_me), split into two clamped
// fp32 factors fixed per group. Zero lanes adopt the nearest nonzero lane's
// frame via a lane-tagged max-scan so frontier mass propagates at full
// precision. Inner loop: 1 shuffle + FMA-pipe ops only. No smem, no barriers.

#define B_      256
#define T_      512
#define V_      256
#define L_      64
#define BLANK_  (V_ - 1)
#define EPS_    1e-7f
#define PF      16
#define FULL_   0xffffffffu

__device__ __forceinline__ float exp2i_clamped(int k) {
    k = max(-126, min(127, k));
    return __int_as_float((k + 127) << 23);
}

__global__ __launch_bounds__(32)
void ctc_kernel(const int* __restrict__ y_true,
                const float* __restrict__ y_pred,
                float* __restrict__ out)
{
    const int b    = blockIdx.x;
    const int lane = threadIdx.x;

    // Labels: state 4l+1 -> y[2l], state 4l+3 -> y[2l+1]
    const int lab0  = y_true[b * L_ + 2 * lane];
    const int lab1  = y_true[b * L_ + 2 * lane + 1];
    const int labm1 = __shfl_up_sync(FULL_, lab1, 1);              // y[2l-1]
    const float sk1 = (lane == 0) ? 1.0f : ((lab0 != labm1) ? 1.0f : 0.0f);
    const float sk3 = (lab1 != lab0) ? 1.0f : 0.0f;

    const float* __restrict__ base = y_pred + (size_t)b * (T_ * V_);

    // Prefetch rings (raw probs) for blank / label0 / label1 columns.
    float qb[PF], q1[PF], q3[PF];
#pragma unroll
    for (int i = 0; i < PF; i++) {
        qb[i] = __ldcs(base + i * V_ + BLANK_);
        q1[i] = __ldcs(base + i * V_ + lab0);
        q3[i] = __ldcs(base + i * V_ + lab1);
    }

    float a0, a1, a2 = 0.f, a3 = 0.f, a4 = 0.f;
    int   E  = 0;                                   // per-lane frame: true = val * 2^E
    float s1 = (lane == 0) ? 0.f : 1.f, s2 = 1.f;   // incoming-a3 reframe factors

#define STEP(pvb, pv1, pv3) do {                                   \
        const float _pb = (pvb) + EPS_;                            \
        const float _p1 = (pv1) + EPS_;                            \
        const float _p3 = (pv3) + EPS_;                            \
        const float a3p = __shfl_up_sync(FULL_, a3, 1);            \
        const float a3q = (a3p * s1) * s2;                         \
        const float n0 = (a0 + a3q) * _pb;                         \
        const float n1 = fmaf(sk1, a3q, a0 + a1) * _p1;            \
        const float n2 = (a1 + a2) * _pb;                          \
        const float n3 = fmaf(sk3, a1, a2 + a3) * _p3;             \
        const float n4 = (a3 + a4) * _pb;                          \
        a0 = n0; a1 = n1; a2 = n2; a3 = n3; a4 = n4;               \
    } while (0)

#define RESCALE() do {                                             \
        float m = fmaxf(fmaxf(a0, a1), fmaxf(a2, a3));             \
        m = fmaxf(m, a4);                                          \
        const bool nz = (m > 0.f);                                 \
        if (nz) {                                                  \
            const int e  = ilogbf(m);                              \
            const int h1 = e >> 1, h2 = e - h1;                    \
            const float u1 = exp2i_clamped(-h1);                   \
            const float u2 = exp2i_clamped(-h2);                   \
            a0 = (a0 * u1) * u2; a1 = (a1 * u1) * u2;              \
            a2 = (a2 * u1) * u2; a3 = (a3 * u1) * u2;              \
            a4 = (a4 * u1) * u2;                                   \
            E += e;                                                \
        }                                                          \
        /* zero lanes adopt nearest-left nonzero lane's frame:     \
           lane-tagged inclusive max-scan */                       \
        int key = nz ? ((lane << 15) | (E + 16384)) : -1;          \
        _Pragma("unroll")                                          \
        for (int off = 1; off < 32; off <<= 1) {                   \
            const int kl = __shfl_up_sync(FULL_, key, off);        \
            if (lane >= off) key = max(key, kl);                   \
        }                                                          \
        if (!nz) E = (key & 32767) - 16384;                        \
        const int Ep = __shfl_up_sync(FULL_, E, 1);                \
        const int dE = Ep - E;                                     \
        const int d1 = dE >> 1, d2 = dE - d1;                      \
        s1 = (lane == 0) ? 0.f : exp2i_clamped(d1);                \
        s2 = exp2i_clamped(d2);                                    \
    } while (0)

    // ---- group 0: t=0 init, t=1..15 steps, refill t=16..31 ----
    a0 = (lane == 0) ? (qb[0] + EPS_) : 0.f;
    a1 = (lane == 0) ? (q1[0] + EPS_) : 0.f;
    qb[0] = __ldcs(base + PF * V_ + BLANK_);
    q1[0] = __ldcs(base + PF * V_ + lab0);
    q3[0] = __ldcs(base + PF * V_ + lab1);
#pragma unroll
    for (int i = 1; i < PF; i++) {
        STEP(qb[i], q1[i], q3[i]);
        qb[i] = __ldcs(base + (i + PF) * V_ + BLANK_);
        q1[i] = __ldcs(base + (i + PF) * V_ + lab0);
        q3[i] = __ldcs(base + (i + PF) * V_ + lab1);
        if (i == 7 || i == 15) RESCALE();
    }

    // ---- middle groups ----
#pragma unroll 1
    for (int tt = PF; tt < T_ - PF; tt += PF) {
#pragma unroll
        for (int i = 0; i < PF; i++) {
            STEP(qb[i], q1[i], q3[i]);
            const int tn = tt + i + PF;
            qb[i] = __ldcs(base + tn * V_ + BLANK_);
            q1[i] = __ldcs(base + tn * V_ + lab0);
            q3[i] = __ldcs(base + tn * V_ + lab1);
            if (i == 7 || i == 15) RESCALE();
        }
    }

    // ---- last group: t = T-16 .. T-1, no refill, no rescale needed ----
#pragma unroll
    for (int i = 0; i < PF; i++) {
        STEP(qb[i], q1[i], q3[i]);
    }

    // loss = -( log(alpha[127] + alpha[128]) + E*ln2 ), states on lane 31
    if (lane == 31) {
        const float tot = a3 + a4;
        out[b] = -(logf(tot) + (float)E * 0.6931471805599453f);
    }

#undef STEP
#undef RESCALE
}

extern "C" void kernel_launch(void* const* d_in, const int* in_sizes, int n_in,
                              void* d_out, int out_size) {
    const int*   y_true = (const int*)  d_in[0];
    const float* y_pred = (const float*)d_in[1];
    float*       out    = (float*)      d_out;
    ctc_kernel<<<B_, 32>>>(y_true, y_pred, out);
}